// round 2
// baseline (speedup 1.0000x reference)
#include <cuda_runtime.h>
#include <cuda_bf16.h>
#include <cstdint>

#define NN 50000
#define EE 800000
#define GG 64
#define RRL 3
#define METAD 38
#define BN_EPS 1e-5f

// ---------------- scratch (device globals; no allocation) ----------------
__device__ float g_buf[NN * 1024];      // GEMM output [N, 4*dout] (204.8 MB)
__device__ float g_actA[NN * 256];      // ping
__device__ float g_actB[NN * 256];      // pong
__device__ float g_ew[EE];              // per-edge 1/cnt weight
__device__ int   g_cnt[RRL * NN];       // (relation,dst) edge counts
__device__ float g_sum[256];
__device__ float g_sumsq[256];
__device__ float g_scale[256];
__device__ float g_shift[256];
__device__ float g_pool[GG * 256];
__device__ int   g_pcnt[GG];

// ---------------- f32x2 helpers ----------------
__device__ __forceinline__ unsigned long long pack2(float lo, float hi) {
    unsigned long long r;
    asm("mov.b64 %0, {%1,%2};" : "=l"(r) : "f"(lo), "f"(hi));
    return r;
}
__device__ __forceinline__ void fma2(unsigned long long& d, unsigned long long a,
                                     unsigned long long b) {
    asm("fma.rn.f32x2 %0, %1, %2, %0;" : "+l"(d) : "l"(a), "l"(b));
}
__device__ __forceinline__ float2 unpack2(unsigned long long v) {
    float2 r;
    asm("mov.b64 {%0,%1}, %2;" : "=f"(r.x), "=f"(r.y) : "l"(v));
    return r;
}

// ---------------- utility kernels ----------------
__global__ void zero_f(float* p, int n) {
    for (int i = blockIdx.x * blockDim.x + threadIdx.x; i < n; i += gridDim.x * blockDim.x)
        p[i] = 0.f;
}
__global__ void zero_i(int* p, int n) {
    for (int i = blockIdx.x * blockDim.x + threadIdx.x; i < n; i += gridDim.x * blockDim.x)
        p[i] = 0;
}

// count edges per (relation, dst)
__global__ void count_kernel(const int* __restrict__ ei, const int* __restrict__ et,
                             int* __restrict__ cnt) {
    int e = blockIdx.x * blockDim.x + threadIdx.x;
    if (e >= EE) return;
    int dst = ei[EE + e];
    int r = et[e];
    atomicAdd(&cnt[r * NN + dst], 1);
}

// per-edge weight = 1/max(cnt,1)
__global__ void edgew_kernel(const int* __restrict__ ei, const int* __restrict__ et,
                             const int* __restrict__ cnt, float* __restrict__ ew) {
    int e = blockIdx.x * blockDim.x + threadIdx.x;
    if (e >= EE) return;
    int dst = ei[EE + e];
    int r = et[e];
    int c = cnt[r * NN + dst];
    ew[e] = 1.0f / (float)max(c, 1);
}

// ---------------- fused GEMM: C[M, 4*dout] = A[M,K] @ [Wroot | Wrel0 | Wrel1 | Wrel2] ----------------
__global__ void __launch_bounds__(256)
gemm_cat(const float* __restrict__ A, const float* __restrict__ Wrel,
         const float* __restrict__ Wroot, float* __restrict__ C,
         int M, int K, int dout) {
    const int BM = 128, BNt = 128, BK = 8;
    __shared__ float As[BK][BM];
    __shared__ float4 Bs[BK][BNt / 4];

    const int Ncols = 4 * dout;
    const int tid = threadIdx.x;
    const int bm = blockIdx.y * BM;
    const int bn = blockIdx.x * BNt;
    const int tx = tid & 15;
    const int ty = tid >> 4;

    unsigned long long acc[8][4];
#pragma unroll
    for (int i = 0; i < 8; i++)
#pragma unroll
        for (int j = 0; j < 4; j++) acc[i][j] = 0ULL;

    const int aRow = tid >> 1;
    const int aCol = (tid & 1) * 4;
    const int bRow = tid >> 5;
    const int bCol = (tid & 31) * 4;

    for (int kt = 0; kt < K; kt += BK) {
        // load A tile (scalar, predicated)
#pragma unroll
        for (int j = 0; j < 4; j++) {
            int m = bm + aRow;
            int k = kt + aCol + j;
            As[aCol + j][aRow] = (m < M && k < K) ? A[(size_t)m * K + k] : 0.f;
        }
        // load B tile via virtual concat mapping (dout%4==0 keeps float4 inside one segment)
        {
            int k = kt + bRow;
            int c = bn + bCol;
            float4 v = make_float4(0.f, 0.f, 0.f, 0.f);
            if (k < K && c < Ncols) {
                int seg = c / dout;
                int cc = c - seg * dout;
                const float* p = (seg == 0)
                                     ? (Wroot + (size_t)k * dout + cc)
                                     : (Wrel + ((size_t)(seg - 1) * K + k) * dout + cc);
                v = *(const float4*)p;
            }
            Bs[bRow][bCol >> 2] = v;
        }
        __syncthreads();
#pragma unroll
        for (int k = 0; k < BK; k++) {
            const float4 a0 = *(const float4*)&As[k][ty * 8];
            const float4 a1 = *(const float4*)&As[k][ty * 8 + 4];
            const float4 b0 = Bs[k][tx * 2];
            const float4 b1 = Bs[k][tx * 2 + 1];
            unsigned long long pb[4];
            pb[0] = pack2(b0.x, b0.y);
            pb[1] = pack2(b0.z, b0.w);
            pb[2] = pack2(b1.x, b1.y);
            pb[3] = pack2(b1.z, b1.w);
            float av[8] = {a0.x, a0.y, a0.z, a0.w, a1.x, a1.y, a1.z, a1.w};
#pragma unroll
            for (int i = 0; i < 8; i++) {
                unsigned long long pa = pack2(av[i], av[i]);
#pragma unroll
                for (int j = 0; j < 4; j++) fma2(acc[i][j], pa, pb[j]);
            }
        }
        __syncthreads();
    }

    // epilogue
#pragma unroll
    for (int i = 0; i < 8; i++) {
        int m = bm + ty * 8 + i;
        if (m >= M) continue;
#pragma unroll
        for (int j = 0; j < 4; j++) {
            int c = bn + tx * 8 + j * 2;
            if (c < Ncols) {
                float2 v = unpack2(acc[i][j]);
                C[(size_t)m * Ncols + c] = v.x;
                C[(size_t)m * Ncols + c + 1] = v.y;
            }
        }
    }
}

// ---------------- init out = root-part + bias (warp per row, vec4) ----------------
__global__ void __launch_bounds__(256)
initbias_kernel(const float* __restrict__ buf, const float* __restrict__ b,
                float* __restrict__ out, int dout) {
    int row = blockIdx.x * 8 + (threadIdx.x >> 5);
    if (row >= NN) return;
    int lane = threadIdx.x & 31;
    const float* in = buf + (size_t)row * (4 * dout);
    float* op = out + (size_t)row * dout;
    for (int c = lane * 4; c < dout; c += 128) {
        float4 v = *(const float4*)(in + c);
        float4 bb = *(const float4*)(b + c);
        v.x += bb.x; v.y += bb.y; v.z += bb.z; v.w += bb.w;
        *(float4*)(op + c) = v;
    }
}

// ---------------- edge scatter: out[dst] += w_e * H[src, (1+r)*dout + c] ----------------
__global__ void __launch_bounds__(256)
scatter_kernel(const int* __restrict__ ei, const int* __restrict__ et,
               const float* __restrict__ ew, const float* __restrict__ buf,
               float* __restrict__ out, int dout) {
    int e = blockIdx.x * 8 + (threadIdx.x >> 5);
    if (e >= EE) return;
    int lane = threadIdx.x & 31;
    int src = ei[e];
    int dst = ei[EE + e];
    int r = et[e];
    float w = ew[e];
    const float* in = buf + (size_t)src * (4 * dout) + (size_t)(r + 1) * dout;
    float* op = out + (size_t)dst * dout;
    for (int c = lane * 4; c < dout; c += 128) {
        float4 v = *(const float4*)(in + c);
        asm volatile("red.global.add.v4.f32 [%0], {%1,%2,%3,%4};" ::"l"(op + c),
                     "f"(v.x * w), "f"(v.y * w), "f"(v.z * w), "f"(v.w * w)
                     : "memory");
    }
}

// ---------------- BN ----------------
__global__ void bn_stats(const float* __restrict__ x, float* __restrict__ sum,
                         float* __restrict__ sumsq, int n, int dout) {
    int c = threadIdx.x;  // blockDim == dout
    float s = 0.f, s2 = 0.f;
    for (int row = blockIdx.x; row < n; row += gridDim.x) {
        float v = x[(size_t)row * dout + c];
        s += v;
        s2 += v * v;
    }
    atomicAdd(&sum[c], s);
    atomicAdd(&sumsq[c], s2);
}

__global__ void bn_finalize(const float* __restrict__ sum, const float* __restrict__ sumsq,
                            const float* __restrict__ g, const float* __restrict__ bb,
                            float* __restrict__ scale, float* __restrict__ shift, int n) {
    int c = threadIdx.x;  // blockDim == dout
    float invn = 1.0f / (float)n;
    float mu = sum[c] * invn;
    float var = sumsq[c] * invn - mu * mu;
    float sc = g[c] * rsqrtf(var + BN_EPS);
    scale[c] = sc;
    shift[c] = bb[c] - mu * sc;
}

__global__ void bn_norm(float* __restrict__ x, const float* __restrict__ scale,
                        const float* __restrict__ shift, int total4, int dout4) {
    for (int i = blockIdx.x * blockDim.x + threadIdx.x; i < total4;
         i += gridDim.x * blockDim.x) {
        int c4 = i % dout4;
        int c = c4 * 4;
        float4 v = ((float4*)x)[i];
        v.x = v.x * scale[c] + shift[c];
        v.y = v.y * scale[c + 1] + shift[c + 1];
        v.z = v.z * scale[c + 2] + shift[c + 2];
        v.w = v.w * scale[c + 3] + shift[c + 3];
        ((float4*)x)[i] = v;
    }
}

// ---------------- pooling ----------------
__global__ void __launch_bounds__(256)
pool_kernel(const float* __restrict__ x, const int* __restrict__ batch,
            float* __restrict__ pool, int* __restrict__ pcnt) {
    int row = blockIdx.x * 8 + (threadIdx.x >> 5);
    if (row >= NN) return;
    int lane = threadIdx.x & 31;
    int g = batch[row];
    const float* in = x + (size_t)row * 256;
    float* op = pool + (size_t)g * 256;
    for (int c = lane * 4; c < 256; c += 128) {
        float4 v = *(const float4*)(in + c);
        asm volatile("red.global.add.v4.f32 [%0], {%1,%2,%3,%4};" ::"l"(op + c),
                     "f"(v.x), "f"(v.y), "f"(v.z), "f"(v.w)
                     : "memory");
    }
    if (lane == 0) atomicAdd(&pcnt[g], 1);
}

// ---------------- final MLP head ----------------
__global__ void final_kernel(const float* __restrict__ pool, const int* __restrict__ pcnt,
                             const float* __restrict__ meta, const float* __restrict__ l1w,
                             const float* __restrict__ l1b, const float* __restrict__ l2w,
                             const float* __restrict__ l2b, float* __restrict__ out) {
    __shared__ float cv[256 + METAD];
    __shared__ float red[128];
    int g = blockIdx.x;
    int t = threadIdx.x;
    float invc = 1.0f / fmaxf((float)pcnt[g], 1.0f);
    for (int c = t; c < 256 + METAD; c += 128)
        cv[c] = (c < 256) ? pool[g * 256 + c] * invc : meta[g * METAD + (c - 256)];
    __syncthreads();
    float val = 0.f;
    if (t < 100) {
        float a = l1b[t];
        for (int i = 0; i < 256 + METAD; i++) a += cv[i] * l1w[i * 100 + t];
        val = a * l2w[t];
    }
    red[t] = val;
    __syncthreads();
    for (int s = 64; s > 0; s >>= 1) {
        if (t < s) red[t] += red[t + s];
        __syncthreads();
    }
    if (t == 0) out[g] = red[0] + l2b[0];
}

// ---------------- host driver ----------------
static void run_layer(const float* hin, int K, int dout, const float* W, const float* Rw,
                      const float* b, const float* gm, const float* bt, float* buf,
                      float* actOut, const int* ei, const int* et, const float* ew,
                      float* sum, float* sumsq, float* scale, float* shift) {
    int Ncols = 4 * dout;
    dim3 grid((Ncols + 127) / 128, (NN + 127) / 128);
    gemm_cat<<<grid, 256>>>(hin, W, Rw, buf, NN, K, dout);
    initbias_kernel<<<(NN + 7) / 8, 256>>>(buf, b, actOut, dout);
    scatter_kernel<<<(EE + 7) / 8, 256>>>(ei, et, ew, buf, actOut, dout);
    zero_f<<<1, 256>>>(sum, 256);
    zero_f<<<1, 256>>>(sumsq, 256);
    bn_stats<<<512, dout>>>(actOut, sum, sumsq, NN, dout);
    bn_finalize<<<1, dout>>>(sum, sumsq, gm, bt, scale, shift, NN);
    int total4 = NN * dout / 4;
    bn_norm<<<2048, 256>>>(actOut, scale, shift, total4, dout / 4);
}

extern "C" void kernel_launch(void* const* d_in, const int* in_sizes, int n_in,
                              void* d_out, int out_size) {
    const float* x = (const float*)d_in[0];
    const int* ei = (const int*)d_in[2];
    const int* et = (const int*)d_in[3];
    const float* meta = (const float*)d_in[4];
    const int* batch = (const int*)d_in[5];
    const float* W[4];
    const float* Rw[4];
    const float* b[4];
    const float* gm[4];
    const float* bt[4];
    int idx = 6;
    for (int l = 0; l < 4; l++) {
        W[l] = (const float*)d_in[idx++];
        Rw[l] = (const float*)d_in[idx++];
        b[l] = (const float*)d_in[idx++];
        gm[l] = (const float*)d_in[idx++];
        bt[l] = (const float*)d_in[idx++];
    }
    const float* l1w = (const float*)d_in[26];
    const float* l1b = (const float*)d_in[27];
    const float* l2w = (const float*)d_in[28];
    const float* l2b = (const float*)d_in[29];
    float* out = (float*)d_out;

    float *buf, *actA, *actB, *ew, *sum, *sumsq, *scale, *shift, *pool;
    int *cnt, *pcnt;
    cudaGetSymbolAddress((void**)&buf, g_buf);
    cudaGetSymbolAddress((void**)&actA, g_actA);
    cudaGetSymbolAddress((void**)&actB, g_actB);
    cudaGetSymbolAddress((void**)&ew, g_ew);
    cudaGetSymbolAddress((void**)&cnt, g_cnt);
    cudaGetSymbolAddress((void**)&sum, g_sum);
    cudaGetSymbolAddress((void**)&sumsq, g_sumsq);
    cudaGetSymbolAddress((void**)&scale, g_scale);
    cudaGetSymbolAddress((void**)&shift, g_shift);
    cudaGetSymbolAddress((void**)&pool, g_pool);
    cudaGetSymbolAddress((void**)&pcnt, g_pcnt);

    // precompute per-edge mean-aggregation weights (input-constant)
    zero_i<<<256, 256>>>(cnt, RRL * NN);
    count_kernel<<<(EE + 255) / 256, 256>>>(ei, et, cnt);
    edgew_kernel<<<(EE + 255) / 256, 256>>>(ei, et, cnt, ew);

    // 4 RGCN layers (ping-pong activations)
    run_layer(x, 128, 100, W[0], Rw[0], b[0], gm[0], bt[0], buf, actA, ei, et, ew, sum,
              sumsq, scale, shift);
    run_layer(actA, 100, 256, W[1], Rw[1], b[1], gm[1], bt[1], buf, actB, ei, et, ew, sum,
              sumsq, scale, shift);
    run_layer(actB, 256, 256, W[2], Rw[2], b[2], gm[2], bt[2], buf, actA, ei, et, ew, sum,
              sumsq, scale, shift);
    run_layer(actA, 256, 256, W[3], Rw[3], b[3], gm[3], bt[3], buf, actB, ei, et, ew, sum,
              sumsq, scale, shift);

    // global mean pool + MLP head
    zero_f<<<64, 256>>>(pool, GG * 256);
    zero_i<<<1, 64>>>(pcnt, GG);
    pool_kernel<<<(NN + 7) / 8, 256>>>(actB, batch, pool, pcnt);
    final_kernel<<<GG, 128>>>(pool, pcnt, meta, l1w, l1b, l2w, l2b, out);
}

// round 5
// speedup vs baseline: 1.3342x; 1.3342x over previous
#include <cuda_runtime.h>
#include <cuda_bf16.h>
#include <cstdint>

#define NN 50000
#define MPAD 50048
#define EE 800000
#define GG 64
#define RRL 3
#define METAD 38
#define BN_EPS 1e-5f

// ---------------- scratch (device globals; no allocation) ----------------
__device__ float g_buf[NN * 1024];              // GEMM output [N, 4*dout] (rel segments)
__device__ float g_actA[NN * 256];              // ping (pre-BN activations)
__device__ float g_actB[NN * 256];              // pong
__device__ __nv_bfloat16 g_Ahi[MPAD * 256];
__device__ __nv_bfloat16 g_Alo[MPAD * 256];
__device__ __nv_bfloat16 g_Bhi[1024 * 256];
__device__ __nv_bfloat16 g_Blo[1024 * 256];
__device__ float g_ew[EE];
__device__ int   g_cnt[RRL * NN];
__device__ float g_sum[256];
__device__ float g_sumsq[256];
__device__ float g_scale[256];
__device__ float g_shift[256];
__device__ float g_pool[GG * 256];
__device__ int   g_pcnt[GG];

// ---------------- PTX helpers (sm_80-level: mma.sync + ldmatrix + cp.async) ----------------
__device__ __forceinline__ uint32_t smem_u32(const void* p) {
    uint32_t a;
    asm("{ .reg .u64 t; cvta.to.shared.u64 t, %1; cvt.u32.u64 %0, t; }" : "=r"(a) : "l"(p));
    return a;
}
__device__ __forceinline__ void ldm4(uint32_t* r, uint32_t addr) {
    asm volatile("ldmatrix.sync.aligned.m8n8.x4.shared.b16 {%0,%1,%2,%3}, [%4];"
                 : "=r"(r[0]), "=r"(r[1]), "=r"(r[2]), "=r"(r[3]) : "r"(addr));
}
__device__ __forceinline__ void mma_bf16(float* d, const uint32_t* a, const uint32_t* b) {
    asm volatile(
        "mma.sync.aligned.m16n8k16.row.col.f32.bf16.bf16.f32 "
        "{%0,%1,%2,%3}, {%4,%5,%6,%7}, {%8,%9}, {%0,%1,%2,%3};"
        : "+f"(d[0]), "+f"(d[1]), "+f"(d[2]), "+f"(d[3])
        : "r"(a[0]), "r"(a[1]), "r"(a[2]), "r"(a[3]), "r"(b[0]), "r"(b[1]));
}
#define CP_ASYNC16(dst, src) \
    asm volatile("cp.async.cg.shared.global [%0], [%1], 16;" ::"r"(dst), "l"(src))
#define CP_COMMIT() asm volatile("cp.async.commit_group;" ::: "memory")
#define CP_WAIT(n) asm volatile("cp.async.wait_group %0;" ::"n"(n) : "memory")

// ---------------- utility kernels ----------------
__global__ void zero_f(float* p, int n) {
    for (int i = blockIdx.x * blockDim.x + threadIdx.x; i < n; i += gridDim.x * blockDim.x)
        p[i] = 0.f;
}
__global__ void zero_i(int* p, int n) {
    for (int i = blockIdx.x * blockDim.x + threadIdx.x; i < n; i += gridDim.x * blockDim.x)
        p[i] = 0;
}
__global__ void count_kernel(const int* __restrict__ ei, const int* __restrict__ et,
                             int* __restrict__ cnt) {
    int e = blockIdx.x * blockDim.x + threadIdx.x;
    if (e >= EE) return;
    atomicAdd(&cnt[et[e] * NN + ei[EE + e]], 1);
}
__global__ void edgew_kernel(const int* __restrict__ ei, const int* __restrict__ et,
                             const int* __restrict__ cnt, float* __restrict__ ew) {
    int e = blockIdx.x * blockDim.x + threadIdx.x;
    if (e >= EE) return;
    int c = cnt[et[e] * NN + ei[EE + e]];
    ew[e] = 1.0f / (float)max(c, 1);
}

// ---------------- conversion: activations -> (hi, lo) bf16, BN fused ----------------
__global__ void convA(const float* __restrict__ act, const float* __restrict__ scale,
                      const float* __restrict__ shift, __nv_bfloat16* __restrict__ Ahi,
                      __nv_bfloat16* __restrict__ Alo, int Kin, int Kpad) {
    int idx = blockIdx.x * blockDim.x + threadIdx.x;  // one bf16x2 pair
    int tot = MPAD * (Kpad >> 1);
    if (idx >= tot) return;
    int m = idx / (Kpad >> 1);
    int k2 = (idx - m * (Kpad >> 1)) * 2;
    float v0 = 0.f, v1 = 0.f;
    if (m < NN && k2 < Kin) {
        v0 = act[(size_t)m * Kin + k2];
        v1 = (k2 + 1 < Kin) ? act[(size_t)m * Kin + k2 + 1] : 0.f;
        if (scale) {
            v0 = v0 * scale[k2] + shift[k2];
            if (k2 + 1 < Kin) v1 = v1 * scale[k2 + 1] + shift[k2 + 1];
        }
    }
    __nv_bfloat16 h0 = __float2bfloat16(v0), h1 = __float2bfloat16(v1);
    __nv_bfloat16 l0 = __float2bfloat16(v0 - __bfloat162float(h0));
    __nv_bfloat16 l1 = __float2bfloat16(v1 - __bfloat162float(h1));
    ((__nv_bfloat162*)Ahi)[idx] = __nv_bfloat162(h0, h1);
    ((__nv_bfloat162*)Alo)[idx] = __nv_bfloat162(l0, l1);
}

// ---------------- conversion: [root|rel0|rel1|rel2] weights -> K-major (hi, lo) ----------------
__global__ void convB(const float* __restrict__ Wrel, const float* __restrict__ Wroot,
                      __nv_bfloat16* __restrict__ Bhi, __nv_bfloat16* __restrict__ Blo,
                      int Kin, int Kpad, int dout, int Npad) {
    int idx = blockIdx.x * blockDim.x + threadIdx.x;
    if (idx >= Npad * Kpad) return;
    int n = idx / Kpad;
    int k = idx - n * Kpad;
    float v = 0.f;
    if (k < Kin && n < 4 * dout) {
        int seg = n / dout;
        int c = n - seg * dout;
        v = (seg == 0) ? Wroot[(size_t)k * dout + c]
                       : Wrel[((size_t)(seg - 1) * Kin + k) * dout + c];
    }
    __nv_bfloat16 h = __float2bfloat16(v);
    Bhi[idx] = h;
    Blo[idx] = __float2bfloat16(v - __bfloat162float(h));
}

// ---------------- mma.sync GEMM: 128x128 tile, bf16 3-split, cp.async double-buffered ----
// C = A @ Bt^T where Bt[n][k]; root segment (cols<dout) -> actOut + bias; rest -> buf
#define BKT 32
#define STRIDE 40                              // bf16 elems per smem row (32 + 8 pad)
#define TILE_B (128 * STRIDE * 2)              // 10240 bytes per array tile
#define STAGE_B (4 * TILE_B)                   // Ahi|Alo|Bhi|Blo = 40960
#define GEMM_SMEM (2 * STAGE_B)                // 81920

__global__ void __launch_bounds__(256, 1)
gemm_mma(const __nv_bfloat16* __restrict__ Ahi, const __nv_bfloat16* __restrict__ Alo,
         const __nv_bfloat16* __restrict__ Bhi, const __nv_bfloat16* __restrict__ Blo,
         float* __restrict__ buf, float* __restrict__ actOut, const float* __restrict__ bias,
         int Kpad, int Ncols, int dout) {
    extern __shared__ char smem[];
    uint32_t sb = smem_u32(smem);
    const int tid = threadIdx.x;
    const int wid = tid >> 5, lane = tid & 31;
    const int bm = blockIdx.y * 128;
    const int bnb = blockIdx.x * 128;
    const int mbase = (wid >> 2) * 64;   // warp 64-row slab
    const int nbase = (wid & 3) * 32;    // warp 32-col slab

    // ldmatrix per-thread row/col offsets
    const int rA = (lane & 7) + ((lane >> 3) & 1) * 8;
    const int kA = (lane >> 4) * 8;
    const int rB = (lane & 7) + ((lane >> 4) & 1) * 8;
    const int kB = ((lane >> 3) & 1) * 8;

    float acc[4][4][4];
#pragma unroll
    for (int mi = 0; mi < 4; mi++)
#pragma unroll
        for (int ni = 0; ni < 4; ni++)
#pragma unroll
            for (int e = 0; e < 4; e++) acc[mi][ni][e] = 0.f;

    const int nIter = Kpad >> 5;  // K chunks of 32
    const size_t rbA = (size_t)Kpad * 2;  // global row bytes

    // stage loader: 4 arrays x 128 rows x 4 chunks(16B); 256 thr -> 2 chunks/thr/array
    const int lrow0 = tid >> 2, lc0 = (tid & 3);
    const int lrow1 = (tid + 256) >> 2, lc1 = ((tid + 256) & 3);
#define LOAD_STAGE(it, stg)                                                                  \
    {                                                                                        \
        int kt = (it)*BKT;                                                                   \
        uint32_t sdst = sb + (stg)*STAGE_B;                                                  \
        const char* gAh = (const char*)Ahi + (size_t)(bm)*rbA + kt * 2;                      \
        const char* gAl = (const char*)Alo + (size_t)(bm)*rbA + kt * 2;                      \
        const char* gBh = (const char*)Bhi + (size_t)(bnb)*rbA + kt * 2;                     \
        const char* gBl = (const char*)Blo + (size_t)(bnb)*rbA + kt * 2;                     \
        CP_ASYNC16(sdst + lrow0 * 80 + lc0 * 16, gAh + (size_t)lrow0 * rbA + lc0 * 16);      \
        CP_ASYNC16(sdst + lrow1 * 80 + lc1 * 16, gAh + (size_t)lrow1 * rbA + lc1 * 16);      \
        CP_ASYNC16(sdst + TILE_B + lrow0 * 80 + lc0 * 16,                                    \
                   gAl + (size_t)lrow0 * rbA + lc0 * 16);                                    \
        CP_ASYNC16(sdst + TILE_B + lrow1 * 80 + lc1 * 16,                                    \
                   gAl + (size_t)lrow1 * rbA + lc1 * 16);                                    \
        CP_ASYNC16(sdst + 2 * TILE_B + lrow0 * 80 + lc0 * 16,                                \
                   gBh + (size_t)lrow0 * rbA + lc0 * 16);                                    \
        CP_ASYNC16(sdst + 2 * TILE_B + lrow1 * 80 + lc1 * 16,                                \
                   gBh + (size_t)lrow1 * rbA + lc1 * 16);                                    \
        CP_ASYNC16(sdst + 3 * TILE_B + lrow0 * 80 + lc0 * 16,                                \
                   gBl + (size_t)lrow0 * rbA + lc0 * 16);                                    \
        CP_ASYNC16(sdst + 3 * TILE_B + lrow1 * 80 + lc1 * 16,                                \
                   gBl + (size_t)lrow1 * rbA + lc1 * 16);                                    \
    }

    LOAD_STAGE(0, 0);
    CP_COMMIT();

    for (int i = 0; i < nIter; i++) {
        if (i + 1 < nIter) {
            LOAD_STAGE(i + 1, (i + 1) & 1);
            CP_COMMIT();
            CP_WAIT(1);
        } else {
            CP_WAIT(0);
        }
        __syncthreads();

        uint32_t sA = sb + (i & 1) * STAGE_B;
        uint32_t sAhi_t = sA + ((mbase + rA) * STRIDE + kA) * 2;
        uint32_t sAlo_t = sAhi_t + TILE_B;
        uint32_t sBhi_t = sA + 2 * TILE_B + ((nbase + rB) * STRIDE + kB) * 2;
        uint32_t sBlo_t = sBhi_t + TILE_B;

#pragma unroll
        for (int kk = 0; kk < 2; kk++) {  // two k16 steps in BK=32
            uint32_t koff = kk * 16 * 2;
            uint32_t Ah[4][4], Al[4][4], Bh[4][2], Bl[4][2];
#pragma unroll
            for (int mi = 0; mi < 4; mi++)
                ldm4(Ah[mi], sAhi_t + mi * 16 * STRIDE * 2 + koff);
            {
                uint32_t t0[4], t1[4];
                ldm4(t0, sBhi_t + koff);
                ldm4(t1, sBhi_t + 16 * STRIDE * 2 + koff);
                Bh[0][0] = t0[0]; Bh[0][1] = t0[1]; Bh[1][0] = t0[2]; Bh[1][1] = t0[3];
                Bh[2][0] = t1[0]; Bh[2][1] = t1[1]; Bh[3][0] = t1[2]; Bh[3][1] = t1[3];
            }
#pragma unroll
            for (int mi = 0; mi < 4; mi++)
#pragma unroll
                for (int ni = 0; ni < 4; ni++) mma_bf16(acc[mi][ni], Ah[mi], Bh[ni]);

#pragma unroll
            for (int mi = 0; mi < 4; mi++)
                ldm4(Al[mi], sAlo_t + mi * 16 * STRIDE * 2 + koff);
#pragma unroll
            for (int mi = 0; mi < 4; mi++)
#pragma unroll
                for (int ni = 0; ni < 4; ni++) mma_bf16(acc[mi][ni], Al[mi], Bh[ni]);

            {
                uint32_t t0[4], t1[4];
                ldm4(t0, sBlo_t + koff);
                ldm4(t1, sBlo_t + 16 * STRIDE * 2 + koff);
                Bl[0][0] = t0[0]; Bl[0][1] = t0[1]; Bl[1][0] = t0[2]; Bl[1][1] = t0[3];
                Bl[2][0] = t1[0]; Bl[2][1] = t1[1]; Bl[3][0] = t1[2]; Bl[3][1] = t1[3];
            }
#pragma unroll
            for (int mi = 0; mi < 4; mi++)
#pragma unroll
                for (int ni = 0; ni < 4; ni++) mma_bf16(acc[mi][ni], Ah[mi], Bl[ni]);
        }
        __syncthreads();
    }

    // epilogue: registers -> global (float2 per atom half)
    const int grp = lane >> 2, q = lane & 3;
#pragma unroll
    for (int mi = 0; mi < 4; mi++) {
#pragma unroll
        for (int half = 0; half < 2; half++) {
            int m = bm + mbase + mi * 16 + grp + half * 8;
            if (m >= NN) continue;
#pragma unroll
            for (int ni = 0; ni < 4; ni++) {
                int gc = bnb + nbase + ni * 8 + q * 2;
                if (gc >= Ncols) continue;
                float v0 = acc[mi][ni][half * 2];
                float v1 = acc[mi][ni][half * 2 + 1];
                if (gc < dout) {
                    v0 += bias[gc];
                    v1 += bias[gc + 1];
                    float2* p = (float2*)(actOut + (size_t)m * dout + gc);
                    *p = make_float2(v0, v1);
                } else {
                    float2* p = (float2*)(buf + (size_t)m * Ncols + gc);
                    *p = make_float2(v0, v1);
                }
            }
        }
    }
}

// ---------------- edge scatter: out[dst] += w_e * buf[src, (1+r)*dout + c] ----------------
__global__ void __launch_bounds__(256)
scatter_kernel(const int* __restrict__ ei, const int* __restrict__ et,
               const float* __restrict__ ew, const float* __restrict__ buf,
               float* __restrict__ out, int dout) {
    int e = blockIdx.x * 8 + (threadIdx.x >> 5);
    if (e >= EE) return;
    int lane = threadIdx.x & 31;
    int src = ei[e];
    int dst = ei[EE + e];
    int r = et[e];
    float w = ew[e];
    const float* in = buf + (size_t)src * (4 * dout) + (size_t)(r + 1) * dout;
    float* op = out + (size_t)dst * dout;
    for (int c = lane * 4; c < dout; c += 128) {
        float4 v = *(const float4*)(in + c);
        asm volatile("red.global.add.v4.f32 [%0], {%1,%2,%3,%4};" ::"l"(op + c),
                     "f"(v.x * w), "f"(v.y * w), "f"(v.z * w), "f"(v.w * w)
                     : "memory");
    }
}

// ---------------- BN stats (norm fused downstream) ----------------
__global__ void bn_stats(const float* __restrict__ x, float* __restrict__ sum,
                         float* __restrict__ sumsq, int n, int dout) {
    int c = threadIdx.x;
    float s = 0.f, s2 = 0.f;
    for (int row = blockIdx.x; row < n; row += gridDim.x) {
        float v = x[(size_t)row * dout + c];
        s += v;
        s2 += v * v;
    }
    atomicAdd(&sum[c], s);
    atomicAdd(&sumsq[c], s2);
}
__global__ void bn_finalize(const float* __restrict__ sum, const float* __restrict__ sumsq,
                            const float* __restrict__ g, const float* __restrict__ bb,
                            float* __restrict__ scale, float* __restrict__ shift, int n) {
    int c = threadIdx.x;
    float invn = 1.0f / (float)n;
    float mu = sum[c] * invn;
    float var = sumsq[c] * invn - mu * mu;
    float sc = g[c] * rsqrtf(var + BN_EPS);
    scale[c] = sc;
    shift[c] = bb[c] - mu * sc;
}

// ---------------- pooling (final BN fused) ----------------
__global__ void __launch_bounds__(256)
pool_kernel(const float* __restrict__ x, const int* __restrict__ batch,
            const float* __restrict__ scale, const float* __restrict__ shift,
            float* __restrict__ pool, int* __restrict__ pcnt) {
    int row = blockIdx.x * 8 + (threadIdx.x >> 5);
    if (row >= NN) return;
    int lane = threadIdx.x & 31;
    int g = batch[row];
    const float* in = x + (size_t)row * 256;
    float* op = pool + (size_t)g * 256;
    for (int c = lane * 4; c < 256; c += 128) {
        float4 v = *(const float4*)(in + c);
        v.x = v.x * scale[c] + shift[c];
        v.y = v.y * scale[c + 1] + shift[c + 1];
        v.z = v.z * scale[c + 2] + shift[c + 2];
        v.w = v.w * scale[c + 3] + shift[c + 3];
        asm volatile("red.global.add.v4.f32 [%0], {%1,%2,%3,%4};" ::"l"(op + c),
                     "f"(v.x), "f"(v.y), "f"(v.z), "f"(v.w)
                     : "memory");
    }
    if (lane == 0) atomicAdd(&pcnt[g], 1);
}

// ---------------- final MLP head ----------------
__global__ void final_kernel(const float* __restrict__ pool, const int* __restrict__ pcnt,
                             const float* __restrict__ meta, const float* __restrict__ l1w,
                             const float* __restrict__ l1b, const float* __restrict__ l2w,
                             const float* __restrict__ l2b, float* __restrict__ out) {
    __shared__ float cv[256 + METAD];
    __shared__ float red[128];
    int g = blockIdx.x;
    int t = threadIdx.x;
    float invc = 1.0f / fmaxf((float)pcnt[g], 1.0f);
    for (int c = t; c < 256 + METAD; c += 128)
        cv[c] = (c < 256) ? pool[g * 256 + c] * invc : meta[g * METAD + (c - 256)];
    __syncthreads();
    float val = 0.f;
    if (t < 100) {
        float a = l1b[t];
        for (int i = 0; i < 256 + METAD; i++) a += cv[i] * l1w[i * 100 + t];
        val = a * l2w[t];
    }
    red[t] = val;
    __syncthreads();
    for (int s = 64; s > 0; s >>= 1) {
        if (t < s) red[t] += red[t + s];
        __syncthreads();
    }
    if (t == 0) out[g] = red[0] + l2b[0];
}

// ---------------- host driver ----------------
struct Ptrs {
    float *buf, *actA, *actB, *ew, *sum, *sumsq, *scale, *shift, *pool;
    __nv_bfloat16 *Ahi, *Alo, *Bhi, *Blo;
    int *cnt, *pcnt;
};

static void run_layer(const float* actIn, const float* scaleIn, const float* shiftIn,
                      int Kin, int Kpad, int dout, const float* W, const float* Rw,
                      const float* b, const float* gm, const float* bt, float* actOut,
                      const int* ei, const int* et, const Ptrs& P) {
    int Npad = (4 * dout + 127) & ~127;
    int Ncols = 4 * dout;
    convA<<<(MPAD * (Kpad / 2) + 255) / 256, 256>>>(actIn, scaleIn, shiftIn, P.Ahi, P.Alo,
                                                    Kin, Kpad);
    convB<<<(Npad * Kpad + 255) / 256, 256>>>(W, Rw, P.Bhi, P.Blo, Kin, Kpad, dout, Npad);
    dim3 grid(Npad / 128, MPAD / 128);
    gemm_mma<<<grid, 256, GEMM_SMEM>>>(P.Ahi, P.Alo, P.Bhi, P.Blo, P.buf, actOut, b, Kpad,
                                       Ncols, dout);
    scatter_kernel<<<(EE + 7) / 8, 256>>>(ei, et, P.ew, P.buf, actOut, dout);
    zero_f<<<1, 256>>>(P.sum, 256);
    zero_f<<<1, 256>>>(P.sumsq, 256);
    bn_stats<<<512, dout>>>(actOut, P.sum, P.sumsq, NN, dout);
    bn_finalize<<<1, dout>>>(P.sum, P.sumsq, gm, bt, P.scale, P.shift, NN);
}

extern "C" void kernel_launch(void* const* d_in, const int* in_sizes, int n_in,
                              void* d_out, int out_size) {
    const float* x = (const float*)d_in[0];
    const int* ei = (const int*)d_in[2];
    const int* et = (const int*)d_in[3];
    const float* meta = (const float*)d_in[4];
    const int* batch = (const int*)d_in[5];
    const float* W[4];
    const float* Rw[4];
    const float* b[4];
    const float* gm[4];
    const float* bt[4];
    int idx = 6;
    for (int l = 0; l < 4; l++) {
        W[l] = (const float*)d_in[idx++];
        Rw[l] = (const float*)d_in[idx++];
        b[l] = (const float*)d_in[idx++];
        gm[l] = (const float*)d_in[idx++];
        bt[l] = (const float*)d_in[idx++];
    }
    const float* l1w = (const float*)d_in[26];
    const float* l1b = (const float*)d_in[27];
    const float* l2w = (const float*)d_in[28];
    const float* l2b = (const float*)d_in[29];
    float* out = (float*)d_out;

    Ptrs P;
    cudaGetSymbolAddress((void**)&P.buf, g_buf);
    cudaGetSymbolAddress((void**)&P.actA, g_actA);
    cudaGetSymbolAddress((void**)&P.actB, g_actB);
    cudaGetSymbolAddress((void**)&P.Ahi, g_Ahi);
    cudaGetSymbolAddress((void**)&P.Alo, g_Alo);
    cudaGetSymbolAddress((void**)&P.Bhi, g_Bhi);
    cudaGetSymbolAddress((void**)&P.Blo, g_Blo);
    cudaGetSymbolAddress((void**)&P.ew, g_ew);
    cudaGetSymbolAddress((void**)&P.cnt, g_cnt);
    cudaGetSymbolAddress((void**)&P.sum, g_sum);
    cudaGetSymbolAddress((void**)&P.sumsq, g_sumsq);
    cudaGetSymbolAddress((void**)&P.scale, g_scale);
    cudaGetSymbolAddress((void**)&P.shift, g_shift);
    cudaGetSymbolAddress((void**)&P.pool, g_pool);
    cudaGetSymbolAddress((void**)&P.pcnt, g_pcnt);

    cudaFuncSetAttribute(gemm_mma, cudaFuncAttributeMaxDynamicSharedMemorySize, GEMM_SMEM);

    // per-edge mean-aggregation weights
    zero_i<<<256, 256>>>(P.cnt, RRL * NN);
    count_kernel<<<(EE + 255) / 256, 256>>>(ei, et, P.cnt);
    edgew_kernel<<<(EE + 255) / 256, 256>>>(ei, et, P.cnt, P.ew);

    // 4 RGCN layers; BN of layer l is fused into layer l+1's convA (or the pool)
    run_layer(x, nullptr, nullptr, 128, 128, 100, W[0], Rw[0], b[0], gm[0], bt[0], P.actA,
              ei, et, P);
    run_layer(P.actA, P.scale, P.shift, 100, 128, 256, W[1], Rw[1], b[1], gm[1], bt[1],
              P.actB, ei, et, P);
    run_layer(P.actB, P.scale, P.shift, 256, 256, 256, W[2], Rw[2], b[2], gm[2], bt[2],
              P.actA, ei, et, P);
    run_layer(P.actA, P.scale, P.shift, 256, 256, 256, W[3], Rw[3], b[3], gm[3], bt[3],
              P.actB, ei, et, P);

    // global mean pool (final BN fused) + MLP head
    zero_f<<<64, 256>>>(P.pool, GG * 256);
    zero_i<<<1, 64>>>(P.pcnt, GG);
    pool_kernel<<<(NN + 7) / 8, 256>>>(P.actB, batch, P.scale, P.shift, P.pool, P.pcnt);
    final_kernel<<<GG, 128>>>(P.pool, P.pcnt, meta, l1w, l1b, l2w, l2b, out);
}

// round 6
// speedup vs baseline: 4.0185x; 3.0120x over previous
#include <cuda_runtime.h>
#include <cuda_fp16.h>
#include <cstdint>

#define NN 50000
#define MPAD 50048
#define EE 800000
#define GG 64
#define RRL 3
#define RN (RRL * NN)
#define METAD 38
#define BN_EPS 1e-5f

// ---------------- scratch (device globals; no allocation) ----------------
__device__ __half g_Ah[MPAD * 1024];   // GEMM A: [M, Kpad] fp16 (root | agg0..2), 102.5MB
__device__ __half g_Bh[256 * 1024];    // GEMM B: [Npad, Kpad] fp16 K-major
__device__ float g_actA[NN * 256];     // ping (pre-BN activations)
__device__ float g_actB[NN * 256];     // pong
__device__ int   g_cnt[RN];            // (relation,dst) edge counts
__device__ int   g_off[RN];            // CSR segment offsets (exclusive scan of cnt)
__device__ int   g_cur[RN];            // fill cursors
__device__ int   g_esrc[EE];           // src node ids sorted by segment
__device__ int   g_bsum[256];          // scan block sums
__device__ float g_sum[256];
__device__ float g_sumsq[256];
__device__ float g_scale[256];
__device__ float g_shift[256];
__device__ float g_pool[GG * 256];
__device__ int   g_pcnt[GG];

// ---------------- PTX helpers ----------------
__device__ __forceinline__ uint32_t smem_u32(const void* p) {
    uint32_t a;
    asm("{ .reg .u64 t; cvta.to.shared.u64 t, %1; cvt.u32.u64 %0, t; }" : "=r"(a) : "l"(p));
    return a;
}
__device__ __forceinline__ void ldm4(uint32_t* r, uint32_t addr) {
    asm volatile("ldmatrix.sync.aligned.m8n8.x4.shared.b16 {%0,%1,%2,%3}, [%4];"
                 : "=r"(r[0]), "=r"(r[1]), "=r"(r[2]), "=r"(r[3]) : "r"(addr));
}
__device__ __forceinline__ void mma_f16(float* d, const uint32_t* a, const uint32_t* b) {
    asm volatile(
        "mma.sync.aligned.m16n8k16.row.col.f32.f16.f16.f32 "
        "{%0,%1,%2,%3}, {%4,%5,%6,%7}, {%8,%9}, {%0,%1,%2,%3};"
        : "+f"(d[0]), "+f"(d[1]), "+f"(d[2]), "+f"(d[3])
        : "r"(a[0]), "r"(a[1]), "r"(a[2]), "r"(a[3]), "r"(b[0]), "r"(b[1]));
}
#define CP_ASYNC16(dst, src) \
    asm volatile("cp.async.cg.shared.global [%0], [%1], 16;" ::"r"(dst), "l"(src))
#define CP_COMMIT() asm volatile("cp.async.commit_group;" ::: "memory")
#define CP_WAIT(n) asm volatile("cp.async.wait_group %0;" ::"n"(n) : "memory")

// ---------------- utility kernels ----------------
__global__ void zero_f(float* p, int n) {
    for (int i = blockIdx.x * blockDim.x + threadIdx.x; i < n; i += gridDim.x * blockDim.x)
        p[i] = 0.f;
}
__global__ void zero_i(int* p, int n) {
    for (int i = blockIdx.x * blockDim.x + threadIdx.x; i < n; i += gridDim.x * blockDim.x)
        p[i] = 0;
}
__global__ void count_kernel(const int* __restrict__ ei, const int* __restrict__ et,
                             int* __restrict__ cnt) {
    int e = blockIdx.x * blockDim.x + threadIdx.x;
    if (e >= EE) return;
    atomicAdd(&cnt[et[e] * NN + ei[EE + e]], 1);
}

// ---------------- CSR build: scan of cnt + permutation ----------------
__global__ void scan1(const int* __restrict__ cnt, int* __restrict__ off,
                      int* __restrict__ bsum, int n) {
    __shared__ int sh[256];
    int tid = threadIdx.x;
    int base = blockIdx.x * 1024;
    int vals[4], tsum = 0;
#pragma unroll
    for (int j = 0; j < 4; j++) {
        int i = base + tid * 4 + j;
        vals[j] = (i < n) ? cnt[i] : 0;
        tsum += vals[j];
    }
    sh[tid] = tsum;
    __syncthreads();
    for (int d = 1; d < 256; d <<= 1) {
        int v = (tid >= d) ? sh[tid - d] : 0;
        __syncthreads();
        sh[tid] += v;
        __syncthreads();
    }
    int run = sh[tid] - tsum;  // exclusive within block
#pragma unroll
    for (int j = 0; j < 4; j++) {
        int i = base + tid * 4 + j;
        if (i < n) off[i] = run;
        run += vals[j];
    }
    if (tid == 255) bsum[blockIdx.x] = sh[255];
}
__global__ void scan2(int* __restrict__ bsum, int nb) {
    __shared__ int sh[256];
    int tid = threadIdx.x;
    int v = (tid < nb) ? bsum[tid] : 0;
    sh[tid] = v;
    __syncthreads();
    for (int d = 1; d < 256; d <<= 1) {
        int u = (tid >= d) ? sh[tid - d] : 0;
        __syncthreads();
        sh[tid] += u;
        __syncthreads();
    }
    if (tid < nb) bsum[tid] = sh[tid] - v;  // exclusive
}
__global__ void scan3(int* __restrict__ off, const int* __restrict__ bsum, int n) {
    int i = blockIdx.x * blockDim.x + threadIdx.x;
    if (i < n) off[i] += bsum[i >> 10];
}
__global__ void fill_kernel(const int* __restrict__ ei, const int* __restrict__ et,
                            const int* __restrict__ off, int* __restrict__ cur,
                            int* __restrict__ esrc) {
    int e = blockIdx.x * blockDim.x + threadIdx.x;
    if (e >= EE) return;
    int seg = et[e] * NN + ei[EE + e];
    int p = off[seg] + atomicAdd(&cur[seg], 1);
    esrc[p] = ei[e];
}

// ---------------- aggregation: warp per (r,dst) segment, write fp16 A directly ----------
// A[m, (1+r)*Kseg + c] = BN(mean over edges of act[src, c])  (0 if empty or pad)
__global__ void __launch_bounds__(256)
agg_kernel(const int* __restrict__ esrc, const int* __restrict__ off,
           const int* __restrict__ cnt, const float* __restrict__ act,
           const float* __restrict__ scale, const float* __restrict__ shift,
           __half* __restrict__ Ah, int din, int Kseg, int Kpad) {
    int s = blockIdx.x * 8 + (threadIdx.x >> 5);
    if (s >= RN) return;
    int lane = threadIdx.x & 31;
    int r = s / NN, dst = s - r * NN;
    int st = off[s], c_ = cnt[s];
    __half* out = Ah + (size_t)dst * Kpad + (size_t)(r + 1) * Kseg;
    for (int c0 = lane * 4; c0 < Kseg; c0 += 128) {
        float4 a = make_float4(0.f, 0.f, 0.f, 0.f);
        if (c0 < din && c_ > 0) {
            for (int i = st; i < st + c_; i++) {
                const float4 v = *(const float4*)(act + (size_t)esrc[i] * din + c0);
                a.x += v.x; a.y += v.y; a.z += v.z; a.w += v.w;
            }
            float inv = 1.0f / (float)c_;
            a.x *= inv; a.y *= inv; a.z *= inv; a.w *= inv;
            if (scale) {
                a.x = a.x * scale[c0] + shift[c0];
                a.y = a.y * scale[c0 + 1] + shift[c0 + 1];
                a.z = a.z * scale[c0 + 2] + shift[c0 + 2];
                a.w = a.w * scale[c0 + 3] + shift[c0 + 3];
            }
        }
        __half2 h0 = __floats2half2_rn(a.x, a.y);
        __half2 h1 = __floats2half2_rn(a.z, a.w);
        *(__half2*)(out + c0) = h0;
        *(__half2*)(out + c0 + 2) = h1;
    }
}

// ---------------- root segment: A[m, c] = BN(act[m, c]) fp16 ----------------
__global__ void rootA_kernel(const float* __restrict__ act, const float* __restrict__ scale,
                             const float* __restrict__ shift, __half* __restrict__ Ah,
                             int din, int Kseg, int Kpad) {
    int idx = blockIdx.x * blockDim.x + threadIdx.x;  // one float4 chunk
    int q = Kseg >> 2;
    if (idx >= NN * q) return;
    int m = idx / q;
    int c0 = (idx - m * q) * 4;
    float4 a = make_float4(0.f, 0.f, 0.f, 0.f);
    if (c0 < din) {
        a = *(const float4*)(act + (size_t)m * din + c0);
        if (scale) {
            a.x = a.x * scale[c0] + shift[c0];
            a.y = a.y * scale[c0 + 1] + shift[c0 + 1];
            a.z = a.z * scale[c0 + 2] + shift[c0 + 2];
            a.w = a.w * scale[c0 + 3] + shift[c0 + 3];
        }
    }
    __half* out = Ah + (size_t)m * Kpad;
    *(__half2*)(out + c0) = __floats2half2_rn(a.x, a.y);
    *(__half2*)(out + c0 + 2) = __floats2half2_rn(a.z, a.w);
}

// ---------------- weights -> K-major fp16: B'[n,k] = [Rw; W0; W1; W2] ----------------
__global__ void convB_h(const float* __restrict__ Wrel, const float* __restrict__ Wroot,
                        __half* __restrict__ Bh, int din, int Kseg, int Kpad, int dout,
                        int Npad) {
    int idx = blockIdx.x * blockDim.x + threadIdx.x;
    if (idx >= Npad * Kpad) return;
    int n = idx / Kpad;
    int k = idx - n * Kpad;
    int seg = k / Kseg, kk = k - seg * Kseg;
    float v = 0.f;
    if (n < dout && kk < din) {
        v = (seg == 0) ? Wroot[(size_t)kk * dout + n]
                       : Wrel[((size_t)(seg - 1) * din + kk) * dout + n];
    }
    Bh[idx] = __float2half(v);
}

// ---------------- fp16 mma GEMM: 128x128 tile, cp.async double-buffered ----------------
// actOut[m, n] = A[m,:] @ B[n,:] + bias[n]
#define BKT 32
#define STRIDE 40                       // fp16 elems per smem row (32 + 8 pad)
#define TILE_B (128 * STRIDE * 2)       // 10240 bytes per array tile
#define STAGE_B (2 * TILE_B)            // A|B = 20480
#define GEMM_SMEM (2 * STAGE_B)         // 40960

__global__ void __launch_bounds__(256, 2)
gemm_h(const __half* __restrict__ A, const __half* __restrict__ B,
       float* __restrict__ actOut, const float* __restrict__ bias, int Kpad, int dout) {
    extern __shared__ char smem[];
    uint32_t sb = smem_u32(smem);
    const int tid = threadIdx.x;
    const int wid = tid >> 5, lane = tid & 31;
    const int bm = blockIdx.y * 128;
    const int bnb = blockIdx.x * 128;
    const int mbase = (wid >> 2) * 64;
    const int nbase = (wid & 3) * 32;

    const int rA = (lane & 7) + ((lane >> 3) & 1) * 8;
    const int kA = (lane >> 4) * 8;
    const int rB = (lane & 7) + ((lane >> 4) & 1) * 8;
    const int kB = ((lane >> 3) & 1) * 8;

    float acc[4][4][4];
#pragma unroll
    for (int mi = 0; mi < 4; mi++)
#pragma unroll
        for (int ni = 0; ni < 4; ni++)
#pragma unroll
            for (int e = 0; e < 4; e++) acc[mi][ni][e] = 0.f;

    const int nIter = Kpad >> 5;
    const size_t rb = (size_t)Kpad * 2;

    const int lrow0 = tid >> 2, lc0 = (tid & 3);
    const int lrow1 = (tid + 256) >> 2;
#define LOAD_STAGE(it, stg)                                                               \
    {                                                                                     \
        int kt = (it)*BKT;                                                                \
        uint32_t sdst = sb + (stg)*STAGE_B;                                               \
        const char* gA = (const char*)A + (size_t)(bm)*rb + kt * 2;                       \
        const char* gB = (const char*)B + (size_t)(bnb)*rb + kt * 2;                      \
        CP_ASYNC16(sdst + lrow0 * 80 + lc0 * 16, gA + (size_t)lrow0 * rb + lc0 * 16);     \
        CP_ASYNC16(sdst + lrow1 * 80 + lc0 * 16, gA + (size_t)lrow1 * rb + lc0 * 16);     \
        CP_ASYNC16(sdst + TILE_B + lrow0 * 80 + lc0 * 16,                                 \
                   gB + (size_t)lrow0 * rb + lc0 * 16);                                   \
        CP_ASYNC16(sdst + TILE_B + lrow1 * 80 + lc0 * 16,                                 \
                   gB + (size_t)lrow1 * rb + lc0 * 16);                                   \
    }

    LOAD_STAGE(0, 0);
    CP_COMMIT();

    for (int i = 0; i < nIter; i++) {
        if (i + 1 < nIter) {
            LOAD_STAGE(i + 1, (i + 1) & 1);
            CP_COMMIT();
            CP_WAIT(1);
        } else {
            CP_WAIT(0);
        }
        __syncthreads();

        uint32_t sA = sb + (i & 1) * STAGE_B;
        uint32_t sA_t = sA + ((mbase + rA) * STRIDE + kA) * 2;
        uint32_t sB_t = sA + TILE_B + ((nbase + rB) * STRIDE + kB) * 2;

#pragma unroll
        for (int kk = 0; kk < 2; kk++) {
            uint32_t koff = kk * 16 * 2;
            uint32_t Af[4][4], Bf[4][2];
#pragma unroll
            for (int mi = 0; mi < 4; mi++)
                ldm4(Af[mi], sA_t + mi * 16 * STRIDE * 2 + koff);
            {
                uint32_t t0[4], t1[4];
                ldm4(t0, sB_t + koff);
                ldm4(t1, sB_t + 16 * STRIDE * 2 + koff);
                Bf[0][0] = t0[0]; Bf[0][1] = t0[1]; Bf[1][0] = t0[2]; Bf[1][1] = t0[3];
                Bf[2][0] = t1[0]; Bf[2][1] = t1[1]; Bf[3][0] = t1[2]; Bf[3][1] = t1[3];
            }
#pragma unroll
            for (int mi = 0; mi < 4; mi++)
#pragma unroll
                for (int ni = 0; ni < 4; ni++) mma_f16(acc[mi][ni], Af[mi], Bf[ni]);
        }
        __syncthreads();
    }

    // epilogue: registers -> actOut (+bias)
    const int grp = lane >> 2, q = lane & 3;
#pragma unroll
    for (int mi = 0; mi < 4; mi++) {
#pragma unroll
        for (int half = 0; half < 2; half++) {
            int m = bm + mbase + mi * 16 + grp + half * 8;
            if (m >= NN) continue;
#pragma unroll
            for (int ni = 0; ni < 4; ni++) {
                int gc = bnb + nbase + ni * 8 + q * 2;
                if (gc >= dout) continue;
                float v0 = acc[mi][ni][half * 2] + bias[gc];
                float v1 = acc[mi][ni][half * 2 + 1] + bias[gc + 1];
                *(float2*)(actOut + (size_t)m * dout + gc) = make_float2(v0, v1);
            }
        }
    }
}

// ---------------- BN stats ----------------
__global__ void bn_stats(const float* __restrict__ x, float* __restrict__ sum,
                         float* __restrict__ sumsq, int n, int dout) {
    int c = threadIdx.x;
    float s = 0.f, s2 = 0.f;
    for (int row = blockIdx.x; row < n; row += gridDim.x) {
        float v = x[(size_t)row * dout + c];
        s += v;
        s2 += v * v;
    }
    atomicAdd(&sum[c], s);
    atomicAdd(&sumsq[c], s2);
}
__global__ void bn_finalize(const float* __restrict__ sum, const float* __restrict__ sumsq,
                            const float* __restrict__ g, const float* __restrict__ bb,
                            float* __restrict__ scale, float* __restrict__ shift, int n) {
    int c = threadIdx.x;
    float invn = 1.0f / (float)n;
    float mu = sum[c] * invn;
    float var = sumsq[c] * invn - mu * mu;
    float sc = g[c] * rsqrtf(var + BN_EPS);
    scale[c] = sc;
    shift[c] = bb[c] - mu * sc;
}

// ---------------- pooling (final BN fused) ----------------
__global__ void __launch_bounds__(256)
pool_kernel(const float* __restrict__ x, const int* __restrict__ batch,
            const float* __restrict__ scale, const float* __restrict__ shift,
            float* __restrict__ pool, int* __restrict__ pcnt) {
    int row = blockIdx.x * 8 + (threadIdx.x >> 5);
    if (row >= NN) return;
    int lane = threadIdx.x & 31;
    int g = batch[row];
    const float* in = x + (size_t)row * 256;
    float* op = pool + (size_t)g * 256;
    for (int c = lane * 4; c < 256; c += 128) {
        float4 v = *(const float4*)(in + c);
        v.x = v.x * scale[c] + shift[c];
        v.y = v.y * scale[c + 1] + shift[c + 1];
        v.z = v.z * scale[c + 2] + shift[c + 2];
        v.w = v.w * scale[c + 3] + shift[c + 3];
        asm volatile("red.global.add.v4.f32 [%0], {%1,%2,%3,%4};" ::"l"(op + c),
                     "f"(v.x), "f"(v.y), "f"(v.z), "f"(v.w)
                     : "memory");
    }
    if (lane == 0) atomicAdd(&pcnt[g], 1);
}

// ---------------- final MLP head ----------------
__global__ void final_kernel(const float* __restrict__ pool, const int* __restrict__ pcnt,
                             const float* __restrict__ meta, const float* __restrict__ l1w,
                             const float* __restrict__ l1b, const float* __restrict__ l2w,
                             const float* __restrict__ l2b, float* __restrict__ out) {
    __shared__ float cv[256 + METAD];
    __shared__ float red[128];
    int g = blockIdx.x;
    int t = threadIdx.x;
    float invc = 1.0f / fmaxf((float)pcnt[g], 1.0f);
    for (int c = t; c < 256 + METAD; c += 128)
        cv[c] = (c < 256) ? pool[g * 256 + c] * invc : meta[g * METAD + (c - 256)];
    __syncthreads();
    float val = 0.f;
    if (t < 100) {
        float a = l1b[t];
        for (int i = 0; i < 256 + METAD; i++) a += cv[i] * l1w[i * 100 + t];
        val = a * l2w[t];
    }
    red[t] = val;
    __syncthreads();
    for (int s = 64; s > 0; s >>= 1) {
        if (t < s) red[t] += red[t + s];
        __syncthreads();
    }
    if (t == 0) out[g] = red[0] + l2b[0];
}

// ---------------- host driver ----------------
struct Ptrs {
    __half *Ah, *Bh;
    float *actA, *actB, *sum, *sumsq, *scale, *shift, *pool;
    int *cnt, *off, *cur, *esrc, *bsum, *pcnt;
};

static void run_layer(const float* actIn, const float* scaleIn, const float* shiftIn,
                      int din, int Kseg, int Kpad, int dout, int Npad, const float* W,
                      const float* Rw, const float* b, const float* gm, const float* bt,
                      float* actOut, const Ptrs& P) {
    agg_kernel<<<(RN + 7) / 8, 256>>>(P.esrc, P.off, P.cnt, actIn, scaleIn, shiftIn, P.Ah,
                                      din, Kseg, Kpad);
    rootA_kernel<<<(NN * (Kseg / 4) + 255) / 256, 256>>>(actIn, scaleIn, shiftIn, P.Ah,
                                                         din, Kseg, Kpad);
    convB_h<<<(Npad * Kpad + 255) / 256, 256>>>(W, Rw, P.Bh, din, Kseg, Kpad, dout, Npad);
    dim3 grid(Npad / 128, MPAD / 128);
    gemm_h<<<grid, 256, GEMM_SMEM>>>(P.Ah, P.Bh, actOut, b, Kpad, dout);
    zero_f<<<1, 256>>>(P.sum, 256);
    zero_f<<<1, 256>>>(P.sumsq, 256);
    bn_stats<<<512, dout>>>(actOut, P.sum, P.sumsq, NN, dout);
    bn_finalize<<<1, dout>>>(P.sum, P.sumsq, gm, bt, P.scale, P.shift, NN);
}

extern "C" void kernel_launch(void* const* d_in, const int* in_sizes, int n_in,
                              void* d_out, int out_size) {
    const float* x = (const float*)d_in[0];
    const int* ei = (const int*)d_in[2];
    const int* et = (const int*)d_in[3];
    const float* meta = (const float*)d_in[4];
    const int* batch = (const int*)d_in[5];
    const float* W[4];
    const float* Rw[4];
    const float* b[4];
    const float* gm[4];
    const float* bt[4];
    int idx = 6;
    for (int l = 0; l < 4; l++) {
        W[l] = (const float*)d_in[idx++];
        Rw[l] = (const float*)d_in[idx++];
        b[l] = (const float*)d_in[idx++];
        gm[l] = (const float*)d_in[idx++];
        bt[l] = (const float*)d_in[idx++];
    }
    const float* l1w = (const float*)d_in[26];
    const float* l1b = (const float*)d_in[27];
    const float* l2w = (const float*)d_in[28];
    const float* l2b = (const float*)d_in[29];
    float* out = (float*)d_out;

    Ptrs P;
    cudaGetSymbolAddress((void**)&P.Ah, g_Ah);
    cudaGetSymbolAddress((void**)&P.Bh, g_Bh);
    cudaGetSymbolAddress((void**)&P.actA, g_actA);
    cudaGetSymbolAddress((void**)&P.actB, g_actB);
    cudaGetSymbolAddress((void**)&P.cnt, g_cnt);
    cudaGetSymbolAddress((void**)&P.off, g_off);
    cudaGetSymbolAddress((void**)&P.cur, g_cur);
    cudaGetSymbolAddress((void**)&P.esrc, g_esrc);
    cudaGetSymbolAddress((void**)&P.bsum, g_bsum);
    cudaGetSymbolAddress((void**)&P.sum, g_sum);
    cudaGetSymbolAddress((void**)&P.sumsq, g_sumsq);
    cudaGetSymbolAddress((void**)&P.scale, g_scale);
    cudaGetSymbolAddress((void**)&P.shift, g_shift);
    cudaGetSymbolAddress((void**)&P.pool, g_pool);
    cudaGetSymbolAddress((void**)&P.pcnt, g_pcnt);

    // CSR build (input-constant per call)
    zero_i<<<256, 256>>>(P.cnt, RN);
    zero_i<<<256, 256>>>(P.cur, RN);
    count_kernel<<<(EE + 255) / 256, 256>>>(ei, et, P.cnt);
    int nb = (RN + 1023) / 1024;  // 147
    scan1<<<nb, 256>>>(P.cnt, P.off, P.bsum, RN);
    scan2<<<1, 256>>>(P.bsum, nb);
    scan3<<<(RN + 255) / 256, 256>>>(P.off, P.bsum, RN);
    fill_kernel<<<(EE + 255) / 256, 256>>>(ei, et, P.off, P.cur, P.esrc);

    // 4 RGCN layers (aggregate-first); BN of layer l folded into layer l+1 inputs
    //            actIn  scale    shift    din Kseg Kpad dout Npad
    run_layer(x,       nullptr, nullptr, 128, 128, 512, 100, 128, W[0], Rw[0], b[0],
              gm[0], bt[0], P.actA, P);
    run_layer(P.actA,  P.scale, P.shift, 100, 128, 512, 256, 256, W[1], Rw[1], b[1],
              gm[1], bt[1], P.actB, P);
    run_layer(P.actB,  P.scale, P.shift, 256, 256, 1024, 256, 256, W[2], Rw[2], b[2],
              gm[2], bt[2], P.actA, P);
    run_layer(P.actA,  P.scale, P.shift, 256, 256, 1024, 256, 256, W[3], Rw[3], b[3],
              gm[3], bt[3], P.actB, P);

    // global mean pool (final BN fused) + MLP head
    zero_f<<<64, 256>>>(P.pool, GG * 256);
    zero_i<<<1, 64>>>(P.pcnt, GG);
    pool_kernel<<<(NN + 7) / 8, 256>>>(P.actB, batch, P.scale, P.shift, P.pool, P.pcnt);
    final_kernel<<<GG, 128>>>(P.pool, P.pcnt, meta, l1w, l1b, l2w, l2b, out);
}

// round 7
// speedup vs baseline: 4.1522x; 1.0333x over previous
#include <cuda_runtime.h>
#include <cuda_fp16.h>
#include <cstdint>

#define NN 50000
#define MPAD 50048
#define EE 800000
#define GG 64
#define RRL 3
#define RN (RRL * NN)
#define METAD 38
#define BN_EPS 1e-5f

// ---------------- scratch (device globals; no allocation) ----------------
__device__ __half g_Ah[MPAD * 1024];   // GEMM A: [M, Kpad] fp16 (root | agg0..2)
__device__ __half g_Bh[256 * 1024];    // GEMM B: [Npad, Kpad] fp16 K-major
__device__ __half g_x16[NN * 128];     // input x converted to fp16
__device__ __half g_actA[NN * 256];    // ping (pre-BN activations, fp16)
__device__ __half g_actB[NN * 256];    // pong
__device__ int   g_cnt[RN];            // (relation,dst) edge counts
__device__ int   g_off[RN];            // CSR segment offsets
__device__ int   g_cur[RN];            // fill cursors
__device__ int   g_esrc[EE];           // src node ids sorted by segment
__device__ int   g_bsum[256];          // scan block sums
__device__ float g_sum[256];
__device__ float g_sumsq[256];
__device__ float g_scale[256];
__device__ float g_shift[256];
__device__ float g_pool[GG * 256];
__device__ int   g_pcnt[GG];

// ---------------- PTX helpers ----------------
__device__ __forceinline__ uint32_t smem_u32(const void* p) {
    uint32_t a;
    asm("{ .reg .u64 t; cvta.to.shared.u64 t, %1; cvt.u32.u64 %0, t; }" : "=r"(a) : "l"(p));
    return a;
}
__device__ __forceinline__ void ldm4(uint32_t* r, uint32_t addr) {
    asm volatile("ldmatrix.sync.aligned.m8n8.x4.shared.b16 {%0,%1,%2,%3}, [%4];"
                 : "=r"(r[0]), "=r"(r[1]), "=r"(r[2]), "=r"(r[3]) : "r"(addr));
}
__device__ __forceinline__ void mma_f16(float* d, const uint32_t* a, const uint32_t* b) {
    asm volatile(
        "mma.sync.aligned.m16n8k16.row.col.f32.f16.f16.f32 "
        "{%0,%1,%2,%3}, {%4,%5,%6,%7}, {%8,%9}, {%0,%1,%2,%3};"
        : "+f"(d[0]), "+f"(d[1]), "+f"(d[2]), "+f"(d[3])
        : "r"(a[0]), "r"(a[1]), "r"(a[2]), "r"(a[3]), "r"(b[0]), "r"(b[1]));
}
#define CP_ASYNC16(dst, src) \
    asm volatile("cp.async.cg.shared.global [%0], [%1], 16;" ::"r"(dst), "l"(src))
#define CP_COMMIT() asm volatile("cp.async.commit_group;" ::: "memory")
#define CP_WAIT(n) asm volatile("cp.async.wait_group %0;" ::"n"(n) : "memory")

// load 4 consecutive halfs (8B) and widen to float4
__device__ __forceinline__ float4 ld_h4(const __half* p) {
    uint2 raw = *(const uint2*)p;
    __half2 h0 = *reinterpret_cast<__half2*>(&raw.x);
    __half2 h1 = *reinterpret_cast<__half2*>(&raw.y);
    float2 f0 = __half22float2(h0), f1 = __half22float2(h1);
    return make_float4(f0.x, f0.y, f1.x, f1.y);
}
__device__ __forceinline__ void st_h4(__half* p, float4 v) {
    uint2 raw;
    __half2 h0 = __floats2half2_rn(v.x, v.y);
    __half2 h1 = __floats2half2_rn(v.z, v.w);
    raw.x = *reinterpret_cast<uint32_t*>(&h0);
    raw.y = *reinterpret_cast<uint32_t*>(&h1);
    *(uint2*)p = raw;
}

// ---------------- utility kernels ----------------
__global__ void zero_f(float* p, int n) {
    for (int i = blockIdx.x * blockDim.x + threadIdx.x; i < n; i += gridDim.x * blockDim.x)
        p[i] = 0.f;
}
__global__ void zero_i(int* p, int n) {
    for (int i = blockIdx.x * blockDim.x + threadIdx.x; i < n; i += gridDim.x * blockDim.x)
        p[i] = 0;
}
__global__ void count_kernel(const int* __restrict__ ei, const int* __restrict__ et,
                             int* __restrict__ cnt) {
    int e = blockIdx.x * blockDim.x + threadIdx.x;
    if (e >= EE) return;
    atomicAdd(&cnt[et[e] * NN + ei[EE + e]], 1);
}
__global__ void conv_x(const float* __restrict__ x, __half* __restrict__ x16, int n) {
    int i = blockIdx.x * blockDim.x + threadIdx.x;
    if (i < n) {
        float2 v = ((const float2*)x)[i];
        ((__half2*)x16)[i] = __floats2half2_rn(v.x, v.y);
    }
}

// ---------------- CSR build ----------------
__global__ void scan1(const int* __restrict__ cnt, int* __restrict__ off,
                      int* __restrict__ bsum, int n) {
    __shared__ int sh[256];
    int tid = threadIdx.x;
    int base = blockIdx.x * 1024;
    int vals[4], tsum = 0;
#pragma unroll
    for (int j = 0; j < 4; j++) {
        int i = base + tid * 4 + j;
        vals[j] = (i < n) ? cnt[i] : 0;
        tsum += vals[j];
    }
    sh[tid] = tsum;
    __syncthreads();
    for (int d = 1; d < 256; d <<= 1) {
        int v = (tid >= d) ? sh[tid - d] : 0;
        __syncthreads();
        sh[tid] += v;
        __syncthreads();
    }
    int run = sh[tid] - tsum;
#pragma unroll
    for (int j = 0; j < 4; j++) {
        int i = base + tid * 4 + j;
        if (i < n) off[i] = run;
        run += vals[j];
    }
    if (tid == 255) bsum[blockIdx.x] = sh[255];
}
__global__ void scan2(int* __restrict__ bsum, int nb) {
    __shared__ int sh[256];
    int tid = threadIdx.x;
    int v = (tid < nb) ? bsum[tid] : 0;
    sh[tid] = v;
    __syncthreads();
    for (int d = 1; d < 256; d <<= 1) {
        int u = (tid >= d) ? sh[tid - d] : 0;
        __syncthreads();
        sh[tid] += u;
        __syncthreads();
    }
    if (tid < nb) bsum[tid] = sh[tid] - v;
}
__global__ void scan3(int* __restrict__ off, const int* __restrict__ bsum, int n) {
    int i = blockIdx.x * blockDim.x + threadIdx.x;
    if (i < n) off[i] += bsum[i >> 10];
}
__global__ void fill_kernel(const int* __restrict__ ei, const int* __restrict__ et,
                            const int* __restrict__ off, int* __restrict__ cur,
                            int* __restrict__ esrc) {
    int e = blockIdx.x * blockDim.x + threadIdx.x;
    if (e >= EE) return;
    int seg = et[e] * NN + ei[EE + e];
    int p = off[seg] + atomicAdd(&cur[seg], 1);
    esrc[p] = ei[e];
}

// ---------------- aggregation: warp per (r,dst) segment, fp16 gather, 2-edge unroll ----
__global__ void __launch_bounds__(256)
agg_kernel(const int* __restrict__ esrc, const int* __restrict__ off,
           const int* __restrict__ cnt, const __half* __restrict__ act,
           const float* __restrict__ scale, const float* __restrict__ shift,
           __half* __restrict__ Ah, int din, int Kseg, int Kpad) {
    int s = blockIdx.x * 8 + (threadIdx.x >> 5);
    if (s >= RN) return;
    int lane = threadIdx.x & 31;
    int r = s / NN, dst = s - r * NN;
    int st = off[s], c_ = cnt[s];
    int e = st + c_;
    __half* out = Ah + (size_t)dst * Kpad + (size_t)(r + 1) * Kseg;
    for (int c0 = lane * 4; c0 < Kseg; c0 += 128) {
        float4 a = make_float4(0.f, 0.f, 0.f, 0.f);
        if (c0 < din && c_ > 0) {
            float4 b = make_float4(0.f, 0.f, 0.f, 0.f);
            int i = st;
            for (; i + 2 <= e; i += 2) {
                int s0 = esrc[i], s1 = esrc[i + 1];
                float4 v0 = ld_h4(act + (size_t)s0 * din + c0);
                float4 v1 = ld_h4(act + (size_t)s1 * din + c0);
                a.x += v0.x; a.y += v0.y; a.z += v0.z; a.w += v0.w;
                b.x += v1.x; b.y += v1.y; b.z += v1.z; b.w += v1.w;
            }
            if (i < e) {
                float4 v0 = ld_h4(act + (size_t)esrc[i] * din + c0);
                a.x += v0.x; a.y += v0.y; a.z += v0.z; a.w += v0.w;
            }
            a.x += b.x; a.y += b.y; a.z += b.z; a.w += b.w;
            float inv = 1.0f / (float)c_;
            a.x *= inv; a.y *= inv; a.z *= inv; a.w *= inv;
            if (scale) {
                a.x = a.x * scale[c0] + shift[c0];
                a.y = a.y * scale[c0 + 1] + shift[c0 + 1];
                a.z = a.z * scale[c0 + 2] + shift[c0 + 2];
                a.w = a.w * scale[c0 + 3] + shift[c0 + 3];
            }
        }
        st_h4(out + c0, a);
    }
}

// ---------------- root segment: A[m, c] = BN(act[m, c]) ----------------
__global__ void rootA_kernel(const __half* __restrict__ act, const float* __restrict__ scale,
                             const float* __restrict__ shift, __half* __restrict__ Ah,
                             int din, int Kseg, int Kpad) {
    int idx = blockIdx.x * blockDim.x + threadIdx.x;  // one 4-half chunk
    int q = Kseg >> 2;
    if (idx >= NN * q) return;
    int m = idx / q;
    int c0 = (idx - m * q) * 4;
    float4 a = make_float4(0.f, 0.f, 0.f, 0.f);
    if (c0 < din) {
        a = ld_h4(act + (size_t)m * din + c0);
        if (scale) {
            a.x = a.x * scale[c0] + shift[c0];
            a.y = a.y * scale[c0 + 1] + shift[c0 + 1];
            a.z = a.z * scale[c0 + 2] + shift[c0 + 2];
            a.w = a.w * scale[c0 + 3] + shift[c0 + 3];
        }
    }
    st_h4(Ah + (size_t)m * Kpad + c0, a);
}

// ---------------- weights -> K-major fp16: B'[n,k] = [Rw; W0; W1; W2] ----------------
__global__ void convB_h(const float* __restrict__ Wrel, const float* __restrict__ Wroot,
                        __half* __restrict__ Bh, int din, int Kseg, int Kpad, int dout,
                        int Npad) {
    int idx = blockIdx.x * blockDim.x + threadIdx.x;
    if (idx >= Npad * Kpad) return;
    int n = idx / Kpad;
    int k = idx - n * Kpad;
    int seg = k / Kseg, kk = k - seg * Kseg;
    float v = 0.f;
    if (n < dout && kk < din) {
        v = (seg == 0) ? Wroot[(size_t)kk * dout + n]
                       : Wrel[((size_t)(seg - 1) * din + kk) * dout + n];
    }
    Bh[idx] = __float2half(v);
}

// ---------------- fp16 mma GEMM: 128x128 tile, cp.async double-buffered ----------------
#define BKT 32
#define STRIDE 40
#define TILE_B (128 * STRIDE * 2)
#define STAGE_B (2 * TILE_B)
#define GEMM_SMEM (2 * STAGE_B)

__global__ void __launch_bounds__(256, 2)
gemm_h(const __half* __restrict__ A, const __half* __restrict__ B,
       __half* __restrict__ actOut, const float* __restrict__ bias, int Kpad, int dout) {
    extern __shared__ char smem[];
    uint32_t sb = smem_u32(smem);
    const int tid = threadIdx.x;
    const int wid = tid >> 5, lane = tid & 31;
    const int bm = blockIdx.y * 128;
    const int bnb = blockIdx.x * 128;
    const int mbase = (wid >> 2) * 64;
    const int nbase = (wid & 3) * 32;

    const int rA = (lane & 7) + ((lane >> 3) & 1) * 8;
    const int kA = (lane >> 4) * 8;
    const int rB = (lane & 7) + ((lane >> 4) & 1) * 8;
    const int kB = ((lane >> 3) & 1) * 8;

    float acc[4][4][4];
#pragma unroll
    for (int mi = 0; mi < 4; mi++)
#pragma unroll
        for (int ni = 0; ni < 4; ni++)
#pragma unroll
            for (int e = 0; e < 4; e++) acc[mi][ni][e] = 0.f;

    const int nIter = Kpad >> 5;
    const size_t rb = (size_t)Kpad * 2;

    const int lrow0 = tid >> 2, lc0 = (tid & 3);
    const int lrow1 = (tid + 256) >> 2;
#define LOAD_STAGE(it, stg)                                                               \
    {                                                                                     \
        int kt = (it)*BKT;                                                                \
        uint32_t sdst = sb + (stg)*STAGE_B;                                               \
        const char* gA = (const char*)A + (size_t)(bm)*rb + kt * 2;                       \
        const char* gB = (const char*)B + (size_t)(bnb)*rb + kt * 2;                      \
        CP_ASYNC16(sdst + lrow0 * 80 + lc0 * 16, gA + (size_t)lrow0 * rb + lc0 * 16);     \
        CP_ASYNC16(sdst + lrow1 * 80 + lc0 * 16, gA + (size_t)lrow1 * rb + lc0 * 16);     \
        CP_ASYNC16(sdst + TILE_B + lrow0 * 80 + lc0 * 16,                                 \
                   gB + (size_t)lrow0 * rb + lc0 * 16);                                   \
        CP_ASYNC16(sdst + TILE_B + lrow1 * 80 + lc0 * 16,                                 \
                   gB + (size_t)lrow1 * rb + lc0 * 16);                                   \
    }

    LOAD_STAGE(0, 0);
    CP_COMMIT();

    for (int i = 0; i < nIter; i++) {
        if (i + 1 < nIter) {
            LOAD_STAGE(i + 1, (i + 1) & 1);
            CP_COMMIT();
            CP_WAIT(1);
        } else {
            CP_WAIT(0);
        }
        __syncthreads();

        uint32_t sA = sb + (i & 1) * STAGE_B;
        uint32_t sA_t = sA + ((mbase + rA) * STRIDE + kA) * 2;
        uint32_t sB_t = sA + TILE_B + ((nbase + rB) * STRIDE + kB) * 2;

#pragma unroll
        for (int kk = 0; kk < 2; kk++) {
            uint32_t koff = kk * 16 * 2;
            uint32_t Af[4][4], Bf[4][2];
#pragma unroll
            for (int mi = 0; mi < 4; mi++)
                ldm4(Af[mi], sA_t + mi * 16 * STRIDE * 2 + koff);
            {
                uint32_t t0[4], t1[4];
                ldm4(t0, sB_t + koff);
                ldm4(t1, sB_t + 16 * STRIDE * 2 + koff);
                Bf[0][0] = t0[0]; Bf[0][1] = t0[1]; Bf[1][0] = t0[2]; Bf[1][1] = t0[3];
                Bf[2][0] = t1[0]; Bf[2][1] = t1[1]; Bf[3][0] = t1[2]; Bf[3][1] = t1[3];
            }
#pragma unroll
            for (int mi = 0; mi < 4; mi++)
#pragma unroll
                for (int ni = 0; ni < 4; ni++) mma_f16(acc[mi][ni], Af[mi], Bf[ni]);
        }
        __syncthreads();
    }

    // epilogue: registers -> actOut fp16 (+bias)
    const int grp = lane >> 2, q = lane & 3;
#pragma unroll
    for (int mi = 0; mi < 4; mi++) {
#pragma unroll
        for (int half = 0; half < 2; half++) {
            int m = bm + mbase + mi * 16 + grp + half * 8;
            if (m >= NN) continue;
#pragma unroll
            for (int ni = 0; ni < 4; ni++) {
                int gc = bnb + nbase + ni * 8 + q * 2;
                if (gc >= dout) continue;
                float v0 = acc[mi][ni][half * 2] + bias[gc];
                float v1 = acc[mi][ni][half * 2 + 1] + bias[gc + 1];
                *(__half2*)(actOut + (size_t)m * dout + gc) = __floats2half2_rn(v0, v1);
            }
        }
    }
}

// ---------------- BN stats (fp16 input, fp32 accum) ----------------
__global__ void bn_stats(const __half* __restrict__ x, float* __restrict__ sum,
                         float* __restrict__ sumsq, int n, int dout) {
    int c = threadIdx.x;
    float s = 0.f, s2 = 0.f;
    for (int row = blockIdx.x; row < n; row += gridDim.x) {
        float v = __half2float(x[(size_t)row * dout + c]);
        s += v;
        s2 += v * v;
    }
    atomicAdd(&sum[c], s);
    atomicAdd(&sumsq[c], s2);
}
__global__ void bn_finalize(const float* __restrict__ sum, const float* __restrict__ sumsq,
                            const float* __restrict__ g, const float* __restrict__ bb,
                            float* __restrict__ scale, float* __restrict__ shift, int n) {
    int c = threadIdx.x;
    float invn = 1.0f / (float)n;
    float mu = sum[c] * invn;
    float var = sumsq[c] * invn - mu * mu;
    float sc = g[c] * rsqrtf(var + BN_EPS);
    scale[c] = sc;
    shift[c] = bb[c] - mu * sc;
}

// ---------------- pooling (final BN fused) ----------------
__global__ void __launch_bounds__(256)
pool_kernel(const __half* __restrict__ x, const int* __restrict__ batch,
            const float* __restrict__ scale, const float* __restrict__ shift,
            float* __restrict__ pool, int* __restrict__ pcnt) {
    int row = blockIdx.x * 8 + (threadIdx.x >> 5);
    if (row >= NN) return;
    int lane = threadIdx.x & 31;
    int g = batch[row];
    const __half* in = x + (size_t)row * 256;
    float* op = pool + (size_t)g * 256;
    for (int c = lane * 4; c < 256; c += 128) {
        float4 v = ld_h4(in + c);
        v.x = v.x * scale[c] + shift[c];
        v.y = v.y * scale[c + 1] + shift[c + 1];
        v.z = v.z * scale[c + 2] + shift[c + 2];
        v.w = v.w * scale[c + 3] + shift[c + 3];
        asm volatile("red.global.add.v4.f32 [%0], {%1,%2,%3,%4};" ::"l"(op + c),
                     "f"(v.x), "f"(v.y), "f"(v.z), "f"(v.w)
                     : "memory");
    }
    if (lane == 0) atomicAdd(&pcnt[g], 1);
}

// ---------------- final MLP head ----------------
__global__ void final_kernel(const float* __restrict__ pool, const int* __restrict__ pcnt,
                             const float* __restrict__ meta, const float* __restrict__ l1w,
                             const float* __restrict__ l1b, const float* __restrict__ l2w,
                             const float* __restrict__ l2b, float* __restrict__ out) {
    __shared__ float cv[256 + METAD];
    __shared__ float red[128];
    int g = blockIdx.x;
    int t = threadIdx.x;
    float invc = 1.0f / fmaxf((float)pcnt[g], 1.0f);
    for (int c = t; c < 256 + METAD; c += 128)
        cv[c] = (c < 256) ? pool[g * 256 + c] * invc : meta[g * METAD + (c - 256)];
    __syncthreads();
    float val = 0.f;
    if (t < 100) {
        float a = l1b[t];
        for (int i = 0; i < 256 + METAD; i++) a += cv[i] * l1w[i * 100 + t];
        val = a * l2w[t];
    }
    red[t] = val;
    __syncthreads();
    for (int s = 64; s > 0; s >>= 1) {
        if (t < s) red[t] += red[t + s];
        __syncthreads();
    }
    if (t == 0) out[g] = red[0] + l2b[0];
}

// ---------------- host driver ----------------
struct Ptrs {
    __half *Ah, *Bh, *x16, *actA, *actB;
    float *sum, *sumsq, *scale, *shift, *pool;
    int *cnt, *off, *cur, *esrc, *bsum, *pcnt;
};

static void run_layer(const __half* actIn, const float* scaleIn, const float* shiftIn,
                      int din, int Kseg, int Kpad, int dout, int Npad, const float* W,
                      const float* Rw, const float* b, const float* gm, const float* bt,
                      __half* actOut, const Ptrs& P) {
    agg_kernel<<<(RN + 7) / 8, 256>>>(P.esrc, P.off, P.cnt, actIn, scaleIn, shiftIn, P.Ah,
                                      din, Kseg, Kpad);
    rootA_kernel<<<(NN * (Kseg / 4) + 255) / 256, 256>>>(actIn, scaleIn, shiftIn, P.Ah,
                                                         din, Kseg, Kpad);
    convB_h<<<(Npad * Kpad + 255) / 256, 256>>>(W, Rw, P.Bh, din, Kseg, Kpad, dout, Npad);
    dim3 grid(Npad / 128, MPAD / 128);
    gemm_h<<<grid, 256, GEMM_SMEM>>>(P.Ah, P.Bh, actOut, b, Kpad, dout);
    zero_f<<<1, 256>>>(P.sum, 256);
    zero_f<<<1, 256>>>(P.sumsq, 256);
    bn_stats<<<512, dout>>>(actOut, P.sum, P.sumsq, NN, dout);
    bn_finalize<<<1, dout>>>(P.sum, P.sumsq, gm, bt, P.scale, P.shift, NN);
}

extern "C" void kernel_launch(void* const* d_in, const int* in_sizes, int n_in,
                              void* d_out, int out_size) {
    const float* x = (const float*)d_in[0];
    const int* ei = (const int*)d_in[2];
    const int* et = (const int*)d_in[3];
    const float* meta = (const float*)d_in[4];
    const int* batch = (const int*)d_in[5];
    const float* W[4];
    const float* Rw[4];
    const float* b[4];
    const float* gm[4];
    const float* bt[4];
    int idx = 6;
    for (int l = 0; l < 4; l++) {
        W[l] = (const float*)d_in[idx++];
        Rw[l] = (const float*)d_in[idx++];
        b[l] = (const float*)d_in[idx++];
        gm[l] = (const float*)d_in[idx++];
        bt[l] = (const float*)d_in[idx++];
    }
    const float* l1w = (const float*)d_in[26];
    const float* l1b = (const float*)d_in[27];
    const float* l2w = (const float*)d_in[28];
    const float* l2b = (const float*)d_in[29];
    float* out = (float*)d_out;

    Ptrs P;
    cudaGetSymbolAddress((void**)&P.Ah, g_Ah);
    cudaGetSymbolAddress((void**)&P.Bh, g_Bh);
    cudaGetSymbolAddress((void**)&P.x16, g_x16);
    cudaGetSymbolAddress((void**)&P.actA, g_actA);
    cudaGetSymbolAddress((void**)&P.actB, g_actB);
    cudaGetSymbolAddress((void**)&P.cnt, g_cnt);
    cudaGetSymbolAddress((void**)&P.off, g_off);
    cudaGetSymbolAddress((void**)&P.cur, g_cur);
    cudaGetSymbolAddress((void**)&P.esrc, g_esrc);
    cudaGetSymbolAddress((void**)&P.bsum, g_bsum);
    cudaGetSymbolAddress((void**)&P.sum, g_sum);
    cudaGetSymbolAddress((void**)&P.sumsq, g_sumsq);
    cudaGetSymbolAddress((void**)&P.scale, g_scale);
    cudaGetSymbolAddress((void**)&P.shift, g_shift);
    cudaGetSymbolAddress((void**)&P.pool, g_pool);
    cudaGetSymbolAddress((void**)&P.pcnt, g_pcnt);

    // CSR build (input-constant per call)
    zero_i<<<256, 256>>>(P.cnt, RN);
    zero_i<<<256, 256>>>(P.cur, RN);
    count_kernel<<<(EE + 255) / 256, 256>>>(ei, et, P.cnt);
    int nb = (RN + 1023) / 1024;  // 147
    scan1<<<nb, 256>>>(P.cnt, P.off, P.bsum, RN);
    scan2<<<1, 256>>>(P.bsum, nb);
    scan3<<<(RN + 255) / 256, 256>>>(P.off, P.bsum, RN);
    fill_kernel<<<(EE + 255) / 256, 256>>>(ei, et, P.off, P.cur, P.esrc);

    // input -> fp16 once
    conv_x<<<(NN * 64 + 255) / 256, 256>>>(x, P.x16, NN * 64);

    // 4 RGCN layers (aggregate-first, fp16 activations)
    //            actIn  scale    shift    din Kseg Kpad dout Npad
    run_layer(P.x16,   nullptr, nullptr, 128, 128, 512, 100, 128, W[0], Rw[0], b[0],
              gm[0], bt[0], P.actA, P);
    run_layer(P.actA,  P.scale, P.shift, 100, 128, 512, 256, 256, W[1], Rw[1], b[1],
              gm[1], bt[1], P.actB, P);
    run_layer(P.actB,  P.scale, P.shift, 256, 256, 1024, 256, 256, W[2], Rw[2], b[2],
              gm[2], bt[2], P.actA, P);
    run_layer(P.actA,  P.scale, P.shift, 256, 256, 1024, 256, 256, W[3], Rw[3], b[3],
              gm[3], bt[3], P.actB, P);

    // global mean pool (final BN fused) + MLP head
    zero_f<<<64, 256>>>(P.pool, GG * 256);
    zero_i<<<1, 64>>>(P.pcnt, GG);
    pool_kernel<<<(NN + 7) / 8, 256>>>(P.actB, batch, P.scale, P.shift, P.pool, P.pcnt);
    final_kernel<<<GG, 128>>>(P.pool, P.pcnt, meta, l1w, l1b, l2w, l2b, out);
}